// round 1
// baseline (speedup 1.0000x reference)
#include <cuda_runtime.h>

// Problem constants
#define NB 8
#define L  2050
#define D  320

// Scratch for y = x @ W : 8*2050*320 floats = 21 MB (device global, no alloc)
__device__ float g_y[NB * L * D];

// ---------------------------------------------------------------------------
// Kernel 1: y[m,e] = sum_d x[m,d] * W[d,e]   (M=16400, N=320, K=320, NN GEMM)
// BM=64, BN=64, BK=16, 256 threads, 4x4 per thread.
// ---------------------------------------------------------------------------
__global__ __launch_bounds__(256) void xw_kernel(const float* __restrict__ X,
                                                 const float* __restrict__ W)
{
    const int M = NB * L;
    __shared__ float As[16 * 64];   // As[k][m]  (transposed)
    __shared__ float Bs[16 * 64];   // Bs[k][n]

    const int t  = threadIdx.x;
    const int tx = t & 15;          // n direction
    const int ty = t >> 4;          // m direction
    const int row0 = blockIdx.y * 64;
    const int col0 = blockIdx.x * 64;

    float acc[4][4];
#pragma unroll
    for (int i = 0; i < 4; i++)
#pragma unroll
        for (int j = 0; j < 4; j++) acc[i][j] = 0.0f;

    for (int k0 = 0; k0 < D; k0 += 16) {
        // Load A tile (64 rows x 16 k), transposed into As[k][m]
        {
            int r  = t >> 2;         // 0..63
            int cq = t & 3;          // float4 index within 16-wide k
            int grow = row0 + r;
            float4 v = make_float4(0.f, 0.f, 0.f, 0.f);
            if (grow < M) v = *reinterpret_cast<const float4*>(&X[(size_t)grow * D + k0 + cq * 4]);
            As[(cq * 4 + 0) * 64 + r] = v.x;
            As[(cq * 4 + 1) * 64 + r] = v.y;
            As[(cq * 4 + 2) * 64 + r] = v.z;
            As[(cq * 4 + 3) * 64 + r] = v.w;
        }
        // Load B tile (16 k-rows x 64 cols) directly
        {
            int kr  = t >> 4;        // 0..15
            int cc4 = t & 15;        // 0..15 (float4 col group)
            float4 v = *reinterpret_cast<const float4*>(&W[(size_t)(k0 + kr) * D + col0 + cc4 * 4]);
            *reinterpret_cast<float4*>(&Bs[kr * 64 + cc4 * 4]) = v;
        }
        __syncthreads();

#pragma unroll
        for (int k = 0; k < 16; k++) {
            float4 a = *reinterpret_cast<const float4*>(&As[k * 64 + ty * 4]);
            float4 b = *reinterpret_cast<const float4*>(&Bs[k * 64 + tx * 4]);
            float av[4] = {a.x, a.y, a.z, a.w};
            float bv[4] = {b.x, b.y, b.z, b.w};
#pragma unroll
            for (int i = 0; i < 4; i++)
#pragma unroll
                for (int j = 0; j < 4; j++) acc[i][j] += av[i] * bv[j];
        }
        __syncthreads();
    }

#pragma unroll
    for (int i = 0; i < 4; i++) {
        int row = row0 + ty * 4 + i;
        if (row >= M) continue;
        float4 v = make_float4(acc[i][0], acc[i][1], acc[i][2], acc[i][3]);
        *reinterpret_cast<float4*>(&g_y[(size_t)row * D + col0 + tx * 4]) = v;
    }
}

// ---------------------------------------------------------------------------
// Kernel 2: out[b,i,j] = sigmoid( sum_e y[b,i,e] * x[b,j,e] + bias )
// Per-batch NT GEMM, M=N=2050, K=320. BM=BN=128, BK=16, 256 threads,
// 8x8 per thread in four 4x4 quadrants (64-split).
// ---------------------------------------------------------------------------
__global__ __launch_bounds__(256) void bilinear_kernel(const float* __restrict__ X,
                                                       const float* __restrict__ bias,
                                                       float* __restrict__ out)
{
    __shared__ float As[16 * 128];  // As[k][i]
    __shared__ float Bs[16 * 128];  // Bs[k][j]

    const int b = blockIdx.z;
    const float* A  = g_y + (size_t)b * L * D;  // y[b]  (rows i)
    const float* Bm = X   + (size_t)b * L * D;  // x[b]  (rows j)

    const int row0 = blockIdx.y * 128;
    const int col0 = blockIdx.x * 128;

    const int t  = threadIdx.x;
    const int tx = t & 15;          // j direction
    const int ty = t >> 4;          // i direction

    float acc[8][8];
#pragma unroll
    for (int i = 0; i < 8; i++)
#pragma unroll
        for (int j = 0; j < 8; j++) acc[i][j] = 0.0f;

    const float biasv = bias[0];

    for (int k0 = 0; k0 < D; k0 += 16) {
        // A tile: 128 rows x 16 k -> 512 float4 slots, 2 per thread, transposed store
#pragma unroll
        for (int s = t; s < 512; s += 256) {
            int r  = s >> 2;     // 0..127
            int cq = s & 3;
            int grow = row0 + r;
            float4 v = make_float4(0.f, 0.f, 0.f, 0.f);
            if (grow < L) v = *reinterpret_cast<const float4*>(&A[(size_t)grow * D + k0 + cq * 4]);
            As[(cq * 4 + 0) * 128 + r] = v.x;
            As[(cq * 4 + 1) * 128 + r] = v.y;
            As[(cq * 4 + 2) * 128 + r] = v.z;
            As[(cq * 4 + 3) * 128 + r] = v.w;
        }
        // B tile: same layout (NT — B rows are j, contiguous in k)
#pragma unroll
        for (int s = t; s < 512; s += 256) {
            int r  = s >> 2;
            int cq = s & 3;
            int grow = col0 + r;
            float4 v = make_float4(0.f, 0.f, 0.f, 0.f);
            if (grow < L) v = *reinterpret_cast<const float4*>(&Bm[(size_t)grow * D + k0 + cq * 4]);
            Bs[(cq * 4 + 0) * 128 + r] = v.x;
            Bs[(cq * 4 + 1) * 128 + r] = v.y;
            Bs[(cq * 4 + 2) * 128 + r] = v.z;
            Bs[(cq * 4 + 3) * 128 + r] = v.w;
        }
        __syncthreads();

#pragma unroll
        for (int k = 0; k < 16; k++) {
            float4 a0 = *reinterpret_cast<const float4*>(&As[k * 128 + ty * 4]);
            float4 a1 = *reinterpret_cast<const float4*>(&As[k * 128 + 64 + ty * 4]);
            float4 b0 = *reinterpret_cast<const float4*>(&Bs[k * 128 + tx * 4]);
            float4 b1 = *reinterpret_cast<const float4*>(&Bs[k * 128 + 64 + tx * 4]);
            float av[8] = {a0.x, a0.y, a0.z, a0.w, a1.x, a1.y, a1.z, a1.w};
            float bv[8] = {b0.x, b0.y, b0.z, b0.w, b1.x, b1.y, b1.z, b1.w};
#pragma unroll
            for (int i = 0; i < 8; i++)
#pragma unroll
                for (int j = 0; j < 8; j++) acc[i][j] += av[i] * bv[j];
        }
        __syncthreads();
    }

    // Epilogue: bias + sigmoid, bounds-checked stores
#pragma unroll
    for (int ih = 0; ih < 2; ih++) {
#pragma unroll
        for (int i = 0; i < 4; i++) {
            int row = row0 + ih * 64 + ty * 4 + i;
            if (row >= L) continue;
            float* orow = out + (size_t)b * L * L + (size_t)row * L;
#pragma unroll
            for (int jh = 0; jh < 2; jh++) {
#pragma unroll
                for (int j = 0; j < 4; j++) {
                    int col = col0 + jh * 64 + tx * 4 + j;
                    if (col < L) {
                        float z = acc[ih * 4 + i][jh * 4 + j] + biasv;
                        orow[col] = 1.0f / (1.0f + __expf(-z));
                    }
                }
            }
        }
    }
}

extern "C" void kernel_launch(void* const* d_in, const int* in_sizes, int n_in,
                              void* d_out, int out_size)
{
    const float* x    = (const float*)d_in[0];   // (8, 2050, 320)
    const float* W    = (const float*)d_in[1];   // (320, 320)
    const float* bias = (const float*)d_in[2];   // (1,)
    float* out = (float*)d_out;                  // (8, 2050, 2050)

    // Stage 1: y = x @ W
    {
        dim3 grid(D / 64, (NB * L + 63) / 64);   // (5, 257)
        xw_kernel<<<grid, 256>>>(x, W);
    }
    // Stage 2: out = sigmoid(y @ x^T + b), per batch
    {
        dim3 grid((L + 127) / 128, (L + 127) / 128, NB);  // (17, 17, 8)
        bilinear_kernel<<<grid, 256>>>(x, bias, out);
    }
}

// round 3
// speedup vs baseline: 1.5427x; 1.5427x over previous
#include <cuda_runtime.h>
#include <cuda_bf16.h>
#include <cstdint>

#define NB 8
#define L  2050
#define D  320
#define KP 960              // packed K = 3*D
#define MTOT (NB * L)

// ---------------------------------------------------------------------------
// Device scratch: packed bf16 operands
//   ypack row = [y_hi(320) | y_hi(320) | y_lo(320)]
//   xpack row = [x_hi(320) | x_lo(320) | x_hi(320)]
// dot(ypack, xpack) = yh·xh + yh·xl + yl·xh  (2-term compensated product)
// ---------------------------------------------------------------------------
__device__ __align__(1024) __nv_bfloat16 g_ypack[MTOT * KP];
__device__ __align__(1024) __nv_bfloat16 g_xpack[MTOT * KP];

__device__ __forceinline__ uint32_t smem_u32(const void* p) {
    uint32_t a;
    asm("{ .reg .u64 t; cvta.to.shared.u64 t, %1; cvt.u32.u64 %0, t; }" : "=r"(a) : "l"(p));
    return a;
}
__device__ __forceinline__ void cp_async16(uint32_t dst, const void* src) {
    asm volatile("cp.async.cg.shared.global [%0], [%1], 16;" :: "r"(dst), "l"(src) : "memory");
}
__device__ __forceinline__ void cp_commit() {
    asm volatile("cp.async.commit_group;" ::: "memory");
}
__device__ __forceinline__ void cp_wait1() {
    asm volatile("cp.async.wait_group 1;" ::: "memory");
}
__device__ __forceinline__ void ldmatrix_x4(uint32_t& r0, uint32_t& r1, uint32_t& r2, uint32_t& r3,
                                            uint32_t addr) {
    asm volatile("ldmatrix.sync.aligned.m8n8.x4.shared.b16 {%0,%1,%2,%3}, [%4];"
                 : "=r"(r0), "=r"(r1), "=r"(r2), "=r"(r3) : "r"(addr));
}
__device__ __forceinline__ void mma16816(float& c0, float& c1, float& c2, float& c3,
                                         uint32_t a0, uint32_t a1, uint32_t a2, uint32_t a3,
                                         uint32_t b0, uint32_t b1) {
    asm volatile("mma.sync.aligned.m16n8k16.row.col.f32.bf16.bf16.f32 "
                 "{%0,%1,%2,%3}, {%4,%5,%6,%7}, {%8,%9}, {%0,%1,%2,%3};"
                 : "+f"(c0), "+f"(c1), "+f"(c2), "+f"(c3)
                 : "r"(a0), "r"(a1), "r"(a2), "r"(a3), "r"(b0), "r"(b1));
}
__device__ __forceinline__ uint32_t sw128(uint32_t off) {  // SW128 swizzle within 1KB atom
    return off ^ ((off >> 3) & 0x70);
}

// ---------------------------------------------------------------------------
// Kernel 0: split x -> xpack  [hi | lo | hi]
// ---------------------------------------------------------------------------
__global__ __launch_bounds__(256) void split_x_kernel(const float* __restrict__ X)
{
    const int N4 = MTOT * D / 4;
    int i4 = blockIdx.x * blockDim.x + threadIdx.x;
    if (i4 >= N4) return;
    float4 v = reinterpret_cast<const float4*>(X)[i4];
    float vv[4] = {v.x, v.y, v.z, v.w};
    __nv_bfloat16 h[4], l[4];
#pragma unroll
    for (int k = 0; k < 4; k++) {
        h[k] = __float2bfloat16(vv[k]);
        l[k] = __float2bfloat16(vv[k] - __bfloat162float(h[k]));
    }
    int row = (i4 * 4) / D;
    int col = (i4 * 4) % D;
    __nv_bfloat16* base = g_xpack + (size_t)row * KP;
    uint2 hv, lv;
    hv.x = (uint32_t)__bfloat16_as_ushort(h[0]) | ((uint32_t)__bfloat16_as_ushort(h[1]) << 16);
    hv.y = (uint32_t)__bfloat16_as_ushort(h[2]) | ((uint32_t)__bfloat16_as_ushort(h[3]) << 16);
    lv.x = (uint32_t)__bfloat16_as_ushort(l[0]) | ((uint32_t)__bfloat16_as_ushort(l[1]) << 16);
    lv.y = (uint32_t)__bfloat16_as_ushort(l[2]) | ((uint32_t)__bfloat16_as_ushort(l[3]) << 16);
    *reinterpret_cast<uint2*>(base + col)       = hv;   // hi
    *reinterpret_cast<uint2*>(base + 320 + col) = lv;   // lo
    *reinterpret_cast<uint2*>(base + 640 + col) = hv;   // hi
}

// ---------------------------------------------------------------------------
// Kernel 1: y = x @ W (fp32 SIMT), epilogue -> ypack [hi | hi | lo]
// ---------------------------------------------------------------------------
__global__ __launch_bounds__(256) void xw_kernel(const float* __restrict__ X,
                                                 const float* __restrict__ W)
{
    __shared__ float As[16 * 64];
    __shared__ float Bs[16 * 64];

    const int t  = threadIdx.x;
    const int tx = t & 15;
    const int ty = t >> 4;
    const int row0 = blockIdx.y * 64;
    const int col0 = blockIdx.x * 64;

    float acc[4][4];
#pragma unroll
    for (int i = 0; i < 4; i++)
#pragma unroll
        for (int j = 0; j < 4; j++) acc[i][j] = 0.0f;

    for (int k0 = 0; k0 < D; k0 += 16) {
        {
            int r  = t >> 2;
            int cq = t & 3;
            int grow = row0 + r;
            float4 v = make_float4(0.f, 0.f, 0.f, 0.f);
            if (grow < MTOT) v = *reinterpret_cast<const float4*>(&X[(size_t)grow * D + k0 + cq * 4]);
            As[(cq * 4 + 0) * 64 + r] = v.x;
            As[(cq * 4 + 1) * 64 + r] = v.y;
            As[(cq * 4 + 2) * 64 + r] = v.z;
            As[(cq * 4 + 3) * 64 + r] = v.w;
        }
        {
            int kr  = t >> 4;
            int cc4 = t & 15;
            float4 v = *reinterpret_cast<const float4*>(&W[(size_t)(k0 + kr) * D + col0 + cc4 * 4]);
            *reinterpret_cast<float4*>(&Bs[kr * 64 + cc4 * 4]) = v;
        }
        __syncthreads();
#pragma unroll
        for (int k = 0; k < 16; k++) {
            float4 a = *reinterpret_cast<const float4*>(&As[k * 64 + ty * 4]);
            float4 b = *reinterpret_cast<const float4*>(&Bs[k * 64 + tx * 4]);
            float av[4] = {a.x, a.y, a.z, a.w};
            float bv[4] = {b.x, b.y, b.z, b.w};
#pragma unroll
            for (int i = 0; i < 4; i++)
#pragma unroll
                for (int j = 0; j < 4; j++) acc[i][j] += av[i] * bv[j];
        }
        __syncthreads();
    }

#pragma unroll
    for (int i = 0; i < 4; i++) {
        int row = row0 + ty * 4 + i;
        if (row >= MTOT) continue;
        __nv_bfloat16* base = g_ypack + (size_t)row * KP;
        uint32_t hp[2], lp[2];
#pragma unroll
        for (int q = 0; q < 2; q++) {
            __nv_bfloat16 h0 = __float2bfloat16(acc[i][q * 2]);
            __nv_bfloat16 h1 = __float2bfloat16(acc[i][q * 2 + 1]);
            __nv_bfloat16 l0 = __float2bfloat16(acc[i][q * 2] - __bfloat162float(h0));
            __nv_bfloat16 l1 = __float2bfloat16(acc[i][q * 2 + 1] - __bfloat162float(h1));
            hp[q] = (uint32_t)__bfloat16_as_ushort(h0) | ((uint32_t)__bfloat16_as_ushort(h1) << 16);
            lp[q] = (uint32_t)__bfloat16_as_ushort(l0) | ((uint32_t)__bfloat16_as_ushort(l1) << 16);
        }
        int col = col0 + tx * 4;
        *reinterpret_cast<uint2*>(base + col)       = make_uint2(hp[0], hp[1]);  // hi
        *reinterpret_cast<uint2*>(base + 320 + col) = make_uint2(hp[0], hp[1]);  // hi
        *reinterpret_cast<uint2*>(base + 640 + col) = make_uint2(lp[0], lp[1]);  // lo
    }
}

// ---------------------------------------------------------------------------
// Kernel 2: out[b,i,j] = sigmoid( ypack[b,i]·xpack[b,j] + bias )
// NT GEMM M=N=2050, K=960, bf16 mma.sync.m16n8k16, fp32 acc.
// BM=BN=128, BK=64 (128B rows, SW128 swizzle), 8 warps of 64x32,
// 2-stage cp.async double buffer.
// ---------------------------------------------------------------------------
#define BK 64
#define STAGE_BYTES 32768                    // (128+128) rows * 128B
#define NKB (KP / BK)                        // 15

__global__ __launch_bounds__(256) void bilinear_mma(const float* __restrict__ bias,
                                                    float* __restrict__ out)
{
    extern __shared__ char smem[];
    const uint32_t sbase = smem_u32(smem);

    const int tid  = threadIdx.x;
    const int wid  = tid >> 5;
    const int lane = tid & 31;

    const int b    = blockIdx.z;
    const int row0 = blockIdx.y * 128;
    const int col0 = blockIdx.x * 128;

    const __nv_bfloat16* Ag = g_ypack + (size_t)b * L * KP;   // rows i
    const __nv_bfloat16* Bg = g_xpack + (size_t)b * L * KP;   // rows j

    // warp tile: 64 (m) x 32 (n)
    const int wm = (wid >> 2) * 64;
    const int wn = (wid & 3) * 32;

    float acc[4][4][4];
#pragma unroll
    for (int mi = 0; mi < 4; mi++)
#pragma unroll
        for (int ni = 0; ni < 4; ni++)
#pragma unroll
            for (int e = 0; e < 4; e++) acc[mi][ni][e] = 0.0f;

    // ---- tile loader: 128 rows x 128B per operand, cp.async 16B granules ----
    auto load_tiles = [&](int kb, int s) {
        const uint32_t stage = sbase + (uint32_t)s * STAGE_BYTES;
        const int koff = kb * BK;                    // bf16 elements
#pragma unroll
        for (int it = tid; it < 1024; it += 256) {   // A: 128 rows x 8 chunks
            int r = it >> 3, c = it & 7;
            uint32_t dst = stage + sw128((uint32_t)(r * 128 + c * 16));
            int grow = row0 + r;
            if (grow < L) cp_async16(dst, Ag + (size_t)grow * KP + koff + c * 8);
            else *reinterpret_cast<uint4*>(smem + (dst - sbase)) = make_uint4(0, 0, 0, 0);
        }
#pragma unroll
        for (int it = tid; it < 1024; it += 256) {   // B
            int r = it >> 3, c = it & 7;
            uint32_t dst = stage + 16384 + sw128((uint32_t)(r * 128 + c * 16));
            int grow = col0 + r;
            if (grow < L) cp_async16(dst, Bg + (size_t)grow * KP + koff + c * 8);
            else *reinterpret_cast<uint4*>(smem + (dst - sbase)) = make_uint4(0, 0, 0, 0);
        }
    };

    load_tiles(0, 0);
    cp_commit();

    for (int kb = 0; kb < NKB; kb++) {
        const int s = kb & 1;
        if (kb + 1 < NKB) load_tiles(kb + 1, s ^ 1);
        cp_commit();
        cp_wait1();
        __syncthreads();

        const uint32_t sA = sbase + (uint32_t)s * STAGE_BYTES;
        const uint32_t sB = sA + 16384;

#pragma unroll
        for (int ks = 0; ks < 4; ks++) {             // 4 k16-steps per block
            // A fragments: 4 m16 tiles
            uint32_t a[4][4];
#pragma unroll
            for (int mi = 0; mi < 4; mi++) {
                int r = wm + mi * 16 + (lane & 7) + ((lane >> 3) & 1) * 8;
                int c = ks * 2 + (lane >> 4);
                ldmatrix_x4(a[mi][0], a[mi][1], a[mi][2], a[mi][3],
                            sA + sw128((uint32_t)(r * 128 + c * 16)));
            }
            // B fragments: 2 x (n16, k16) -> 4 n8 tiles
            uint32_t bf[2][4];
#pragma unroll
            for (int nj = 0; nj < 2; nj++) {
                int n = wn + nj * 16 + (lane & 7) + (lane >> 4) * 8;
                int c = ks * 2 + ((lane >> 3) & 1);
                ldmatrix_x4(bf[nj][0], bf[nj][1], bf[nj][2], bf[nj][3],
                            sB + sw128((uint32_t)(n * 128 + c * 16)));
            }
#pragma unroll
            for (int mi = 0; mi < 4; mi++)
#pragma unroll
                for (int ni = 0; ni < 4; ni++) {
                    uint32_t b0 = bf[ni >> 1][(ni & 1) * 2];
                    uint32_t b1 = bf[ni >> 1][(ni & 1) * 2 + 1];
                    mma16816(acc[mi][ni][0], acc[mi][ni][1], acc[mi][ni][2], acc[mi][ni][3],
                             a[mi][0], a[mi][1], a[mi][2], a[mi][3], b0, b1);
                }
        }
        __syncthreads();
    }

    // ---- epilogue: bias + sigmoid ----
    const float biasv = bias[0];
    float* obase = out + (size_t)b * L * L;
#pragma unroll
    for (int mi = 0; mi < 4; mi++) {
        int r0 = row0 + wm + mi * 16 + (lane >> 2);
#pragma unroll
        for (int ni = 0; ni < 4; ni++) {
            int col = col0 + wn + ni * 8 + (lane & 3) * 2;
            if (col >= L) continue;
#pragma unroll
            for (int h = 0; h < 2; h++) {           // h=0: rows r0, h=1: rows r0+8
                int row = r0 + h * 8;
                if (row >= L) continue;
                float z0 = acc[mi][ni][h * 2]     + biasv;
                float z1 = acc[mi][ni][h * 2 + 1] + biasv;
                float2 o;
                o.x = 1.0f / (1.0f + __expf(-z0));
                o.y = 1.0f / (1.0f + __expf(-z1));
                *reinterpret_cast<float2*>(&obase[(size_t)row * L + col]) = o;
            }
        }
    }
}

// ---------------------------------------------------------------------------
extern "C" void kernel_launch(void* const* d_in, const int* in_sizes, int n_in,
                              void* d_out, int out_size)
{
    const float* x    = (const float*)d_in[0];   // (8, 2050, 320)
    const float* W    = (const float*)d_in[1];   // (320, 320)
    const float* bias = (const float*)d_in[2];   // (1,)
    float* out = (float*)d_out;                  // (8, 2050, 2050)

    cudaFuncSetAttribute(bilinear_mma, cudaFuncAttributeMaxDynamicSharedMemorySize,
                         2 * STAGE_BYTES);

    {
        int n4 = MTOT * D / 4;
        split_x_kernel<<<(n4 + 255) / 256, 256>>>(x);
    }
    {
        dim3 grid(D / 64, (MTOT + 63) / 64);
        xw_kernel<<<grid, 256>>>(x, W);
    }
    {
        dim3 grid((L + 127) / 128, (L + 127) / 128, NB);  // (17,17,8)
        bilinear_mma<<<grid, 256, 2 * STAGE_BYTES>>>(bias, out);
    }
}

// round 4
// speedup vs baseline: 1.6850x; 1.0922x over previous
#include <cuda_runtime.h>
#include <cuda_bf16.h>
#include <cstdint>

#define NB 8
#define L  2050
#define D  320
#define KP 960              // packed K = 3*D
#define MTOT (NB * L)

// ---------------------------------------------------------------------------
// Device scratch (bf16 packed operands)
//   xpack row = [x_hi(320) | x_lo(320) | x_hi(320)]
//   ypack row = [y_hi(320) | y_hi(320) | y_lo(320)]
//   wpack row e = [Wh^T(320) | Wh^T(320+) ... ] -> [Wh | Wh | Wl] of column e
// dot(ypack_i, xpack_j) = yh·xh + yh·xl + yl·xh
// dot(xpack_m, wpack_e) = xh·Wh + xl·Wh + xh·Wl
// ---------------------------------------------------------------------------
__device__ __align__(1024) __nv_bfloat16 g_xpack[MTOT * KP];
__device__ __align__(1024) __nv_bfloat16 g_ypack[MTOT * KP];
__device__ __align__(1024) __nv_bfloat16 g_wpack[D * KP];

__device__ __forceinline__ uint32_t smem_u32(const void* p) {
    uint32_t a;
    asm("{ .reg .u64 t; cvta.to.shared.u64 t, %1; cvt.u32.u64 %0, t; }" : "=r"(a) : "l"(p));
    return a;
}
__device__ __forceinline__ void cp_async16(uint32_t dst, const void* src) {
    asm volatile("cp.async.cg.shared.global [%0], [%1], 16;" :: "r"(dst), "l"(src) : "memory");
}
__device__ __forceinline__ void cp_commit() {
    asm volatile("cp.async.commit_group;" ::: "memory");
}
__device__ __forceinline__ void cp_wait0() {
    asm volatile("cp.async.wait_group 0;" ::: "memory");
}
__device__ __forceinline__ void ldmatrix_x4(uint32_t& r0, uint32_t& r1, uint32_t& r2, uint32_t& r3,
                                            uint32_t addr) {
    asm volatile("ldmatrix.sync.aligned.m8n8.x4.shared.b16 {%0,%1,%2,%3}, [%4];"
                 : "=r"(r0), "=r"(r1), "=r"(r2), "=r"(r3) : "r"(addr));
}
__device__ __forceinline__ void mma16816(float* c,
                                         const uint32_t* a, uint32_t b0, uint32_t b1) {
    asm volatile("mma.sync.aligned.m16n8k16.row.col.f32.bf16.bf16.f32 "
                 "{%0,%1,%2,%3}, {%4,%5,%6,%7}, {%8,%9}, {%0,%1,%2,%3};"
                 : "+f"(c[0]), "+f"(c[1]), "+f"(c[2]), "+f"(c[3])
                 : "r"(a[0]), "r"(a[1]), "r"(a[2]), "r"(a[3]), "r"(b0), "r"(b1));
}
__device__ __forceinline__ uint32_t sw128(uint32_t off) {
    return off ^ ((off >> 3) & 0x70);
}
__device__ __forceinline__ uint32_t pack_bf2(__nv_bfloat16 a, __nv_bfloat16 b) {
    return (uint32_t)__bfloat16_as_ushort(a) | ((uint32_t)__bfloat16_as_ushort(b) << 16);
}

// ---------------------------------------------------------------------------
// Kernel 0: split x -> xpack [hi | lo | hi]
// ---------------------------------------------------------------------------
__global__ __launch_bounds__(256) void split_x_kernel(const float* __restrict__ X)
{
    const int N4 = MTOT * D / 4;
    int i4 = blockIdx.x * blockDim.x + threadIdx.x;
    if (i4 >= N4) return;
    float4 v = reinterpret_cast<const float4*>(X)[i4];
    float vv[4] = {v.x, v.y, v.z, v.w};
    __nv_bfloat16 h[4], l[4];
#pragma unroll
    for (int k = 0; k < 4; k++) {
        h[k] = __float2bfloat16(vv[k]);
        l[k] = __float2bfloat16(vv[k] - __bfloat162float(h[k]));
    }
    int row = (i4 * 4) / D;
    int col = (i4 * 4) % D;
    __nv_bfloat16* base = g_xpack + (size_t)row * KP;
    uint2 hv = make_uint2(pack_bf2(h[0], h[1]), pack_bf2(h[2], h[3]));
    uint2 lv = make_uint2(pack_bf2(l[0], l[1]), pack_bf2(l[2], l[3]));
    *reinterpret_cast<uint2*>(base + col)       = hv;
    *reinterpret_cast<uint2*>(base + 320 + col) = lv;
    *reinterpret_cast<uint2*>(base + 640 + col) = hv;
}

// ---------------------------------------------------------------------------
// Kernel 0b: pack W -> wpack; row e = [Wh(:,e) | Wh(:,e) | Wl(:,e)] (k-major d)
// ---------------------------------------------------------------------------
__global__ __launch_bounds__(256) void pack_w_kernel(const float* __restrict__ W)
{
    int i = blockIdx.x * blockDim.x + threadIdx.x;   // over D*D
    if (i >= D * D) return;
    int d = i / D, e = i % D;
    float w = W[(size_t)d * D + e];
    __nv_bfloat16 h = __float2bfloat16(w);
    __nv_bfloat16 l = __float2bfloat16(w - __bfloat162float(h));
    __nv_bfloat16* base = g_wpack + (size_t)e * KP;
    base[d]       = h;
    base[320 + d] = h;
    base[640 + d] = l;
}

// ---------------------------------------------------------------------------
// Kernel 1: y = x @ W via bf16 split mma. NT GEMM: A=xpack (16400,960),
// B=wpack (320,960). CTA 128x64, 8 warps (4m x 2n), warp tile 32x32.
// Epilogue writes ypack [hi|hi|lo].
// ---------------------------------------------------------------------------
#define XW_STAGE ((128 + 64) * 128)              // 24576 B per stage

__global__ __launch_bounds__(256) void xw_mma(void)
{
    extern __shared__ char smem[];
    const uint32_t sbase = smem_u32(smem);
    const int tid  = threadIdx.x;
    const int wid  = tid >> 5;
    const int lane = tid & 31;

    const int row0 = blockIdx.y * 128;
    const int col0 = blockIdx.x * 64;

    const int wm = (wid >> 1) * 32;
    const int wn = (wid & 1) * 32;

    float acc[2][4][4];
#pragma unroll
    for (int mi = 0; mi < 2; mi++)
#pragma unroll
        for (int ni = 0; ni < 4; ni++)
#pragma unroll
            for (int e = 0; e < 4; e++) acc[mi][ni][e] = 0.0f;

    auto load_tiles = [&](int kb, int s) {
        const uint32_t stage = sbase + (uint32_t)s * XW_STAGE;
        const int koff = kb * 64;
#pragma unroll
        for (int it = tid; it < 1024; it += 256) {       // A: 128 rows x 8
            int r = it >> 3, c = it & 7;
            uint32_t dst = stage + sw128((uint32_t)(r * 128 + c * 16));
            int grow = row0 + r;
            if (grow < MTOT) cp_async16(dst, g_xpack + (size_t)grow * KP + koff + c * 8);
            else *reinterpret_cast<uint4*>(smem + (dst - sbase)) = make_uint4(0, 0, 0, 0);
        }
#pragma unroll
        for (int it = tid; it < 512; it += 256) {        // B: 64 rows x 8 (always in-bounds)
            int r = it >> 3, c = it & 7;
            uint32_t dst = stage + 16384 + sw128((uint32_t)(r * 128 + c * 16));
            cp_async16(dst, g_wpack + (size_t)(col0 + r) * KP + koff + c * 8);
        }
    };

    load_tiles(0, 0);
    cp_commit();

    for (int kb = 0; kb < KP / 64; kb++) {
        const int s = kb & 1;
        cp_wait0();
        __syncthreads();
        if (kb + 1 < KP / 64) { load_tiles(kb + 1, s ^ 1); cp_commit(); }

        const uint32_t sA = sbase + (uint32_t)s * XW_STAGE;
        const uint32_t sB = sA + 16384;
#pragma unroll
        for (int ks = 0; ks < 4; ks++) {
            uint32_t a[2][4];
#pragma unroll
            for (int mi = 0; mi < 2; mi++) {
                int r = wm + mi * 16 + (lane & 7) + ((lane >> 3) & 1) * 8;
                int c = ks * 2 + (lane >> 4);
                ldmatrix_x4(a[mi][0], a[mi][1], a[mi][2], a[mi][3],
                            sA + sw128((uint32_t)(r * 128 + c * 16)));
            }
#pragma unroll
            for (int nj = 0; nj < 2; nj++) {
                uint32_t bf[4];
                int n = wn + nj * 16 + (lane & 7) + (lane >> 4) * 8;
                int c = ks * 2 + ((lane >> 3) & 1);
                ldmatrix_x4(bf[0], bf[1], bf[2], bf[3],
                            sB + sw128((uint32_t)(n * 128 + c * 16)));
#pragma unroll
                for (int mi = 0; mi < 2; mi++) {
                    mma16816(acc[mi][nj * 2],     a[mi], bf[0], bf[1]);
                    mma16816(acc[mi][nj * 2 + 1], a[mi], bf[2], bf[3]);
                }
            }
        }
        __syncthreads();
    }

    // Epilogue: split y into ypack [hi | hi | lo]
#pragma unroll
    for (int mi = 0; mi < 2; mi++) {
        int r0 = row0 + wm + mi * 16 + (lane >> 2);
#pragma unroll
        for (int ni = 0; ni < 4; ni++) {
            int col = col0 + wn + ni * 8 + (lane & 3) * 2;
#pragma unroll
            for (int h = 0; h < 2; h++) {
                int row = r0 + h * 8;
                if (row >= MTOT) continue;
                float v0 = acc[mi][ni][h * 2];
                float v1 = acc[mi][ni][h * 2 + 1];
                __nv_bfloat16 h0 = __float2bfloat16(v0);
                __nv_bfloat16 h1 = __float2bfloat16(v1);
                __nv_bfloat16 l0 = __float2bfloat16(v0 - __bfloat162float(h0));
                __nv_bfloat16 l1 = __float2bfloat16(v1 - __bfloat162float(h1));
                uint32_t hp = pack_bf2(h0, h1);
                uint32_t lp = pack_bf2(l0, l1);
                __nv_bfloat16* base = g_ypack + (size_t)row * KP;
                *reinterpret_cast<uint32_t*>(base + col)       = hp;
                *reinterpret_cast<uint32_t*>(base + 320 + col) = hp;
                *reinterpret_cast<uint32_t*>(base + 640 + col) = lp;
            }
        }
    }
}

// ---------------------------------------------------------------------------
// Kernel 2: out[b,i,j] = sigmoid( ypack[b,i]·xpack[b,j] + bias )
// NT GEMM M=N=2050, K=960. CTA 128x256, 8 warps (2m x 4n), warp tile 64x64.
// 2-stage cp.async pipeline, SW128 smem, bf16 HMMA, fp32 acc.
// ---------------------------------------------------------------------------
#define BL_STAGE ((128 + 256) * 128)             // 49152 B per stage
#define NKB (KP / 64)                            // 15

__global__ __launch_bounds__(256) void bilinear_mma(const float* __restrict__ bias,
                                                    float* __restrict__ out)
{
    extern __shared__ char smem[];
    const uint32_t sbase = smem_u32(smem);
    const int tid  = threadIdx.x;
    const int wid  = tid >> 5;
    const int lane = tid & 31;

    const int b    = blockIdx.z;
    const int row0 = blockIdx.y * 128;
    const int col0 = blockIdx.x * 256;

    const __nv_bfloat16* Ag = g_ypack + (size_t)b * L * KP;
    const __nv_bfloat16* Bg = g_xpack + (size_t)b * L * KP;

    const int wm = (wid >> 2) * 64;      // 2 m-positions
    const int wn = (wid & 3) * 64;       // 4 n-positions

    float acc[4][8][4];
#pragma unroll
    for (int mi = 0; mi < 4; mi++)
#pragma unroll
        for (int ni = 0; ni < 8; ni++)
#pragma unroll
            for (int e = 0; e < 4; e++) acc[mi][ni][e] = 0.0f;

    auto load_tiles = [&](int kb, int s) {
        const uint32_t stage = sbase + (uint32_t)s * BL_STAGE;
        const int koff = kb * 64;
#pragma unroll
        for (int it = tid; it < 1024; it += 256) {       // A: 128 rows x 8
            int r = it >> 3, c = it & 7;
            uint32_t dst = stage + sw128((uint32_t)(r * 128 + c * 16));
            int grow = row0 + r;
            if (grow < L) cp_async16(dst, Ag + (size_t)grow * KP + koff + c * 8);
            else *reinterpret_cast<uint4*>(smem + (dst - sbase)) = make_uint4(0, 0, 0, 0);
        }
#pragma unroll
        for (int it = tid; it < 2048; it += 256) {       // B: 256 rows x 8
            int r = it >> 3, c = it & 7;
            uint32_t dst = stage + 16384 + sw128((uint32_t)(r * 128 + c * 16));
            int grow = col0 + r;
            if (grow < L) cp_async16(dst, Bg + (size_t)grow * KP + koff + c * 8);
            else *reinterpret_cast<uint4*>(smem + (dst - sbase)) = make_uint4(0, 0, 0, 0);
        }
    };

    load_tiles(0, 0);
    cp_commit();

    for (int kb = 0; kb < NKB; kb++) {
        const int s = kb & 1;
        cp_wait0();
        __syncthreads();
        if (kb + 1 < NKB) { load_tiles(kb + 1, s ^ 1); cp_commit(); }

        const uint32_t sA = sbase + (uint32_t)s * BL_STAGE;
        const uint32_t sB = sA + 16384;

#pragma unroll
        for (int ks = 0; ks < 4; ks++) {
            uint32_t a[4][4];
#pragma unroll
            for (int mi = 0; mi < 4; mi++) {
                int r = wm + mi * 16 + (lane & 7) + ((lane >> 3) & 1) * 8;
                int c = ks * 2 + (lane >> 4);
                ldmatrix_x4(a[mi][0], a[mi][1], a[mi][2], a[mi][3],
                            sA + sw128((uint32_t)(r * 128 + c * 16)));
            }
#pragma unroll
            for (int nj = 0; nj < 4; nj++) {
                uint32_t bf[4];
                int n = wn + nj * 16 + (lane & 7) + (lane >> 4) * 8;
                int c = ks * 2 + ((lane >> 3) & 1);
                ldmatrix_x4(bf[0], bf[1], bf[2], bf[3],
                            sB + sw128((uint32_t)(n * 128 + c * 16)));
#pragma unroll
                for (int mi = 0; mi < 4; mi++) {
                    mma16816(acc[mi][nj * 2],     a[mi], bf[0], bf[1]);
                    mma16816(acc[mi][nj * 2 + 1], a[mi], bf[2], bf[3]);
                }
            }
        }
        __syncthreads();
    }

    // Epilogue: bias + sigmoid
    const float biasv = bias[0];
    float* obase = out + (size_t)b * L * L;
#pragma unroll
    for (int mi = 0; mi < 4; mi++) {
        int r0 = row0 + wm + mi * 16 + (lane >> 2);
#pragma unroll
        for (int ni = 0; ni < 8; ni++) {
            int col = col0 + wn + ni * 8 + (lane & 3) * 2;
            if (col >= L) continue;
#pragma unroll
            for (int h = 0; h < 2; h++) {
                int row = r0 + h * 8;
                if (row >= L) continue;
                float z0 = acc[mi][ni][h * 2]     + biasv;
                float z1 = acc[mi][ni][h * 2 + 1] + biasv;
                float2 o;
                o.x = 1.0f / (1.0f + __expf(-z0));
                o.y = 1.0f / (1.0f + __expf(-z1));
                *reinterpret_cast<float2*>(&obase[(size_t)row * L + col]) = o;
            }
        }
    }
}

// ---------------------------------------------------------------------------
extern "C" void kernel_launch(void* const* d_in, const int* in_sizes, int n_in,
                              void* d_out, int out_size)
{
    const float* x    = (const float*)d_in[0];   // (8, 2050, 320)
    const float* W    = (const float*)d_in[1];   // (320, 320)
    const float* bias = (const float*)d_in[2];   // (1,)
    float* out = (float*)d_out;                  // (8, 2050, 2050)

    cudaFuncSetAttribute(xw_mma, cudaFuncAttributeMaxDynamicSharedMemorySize, 2 * XW_STAGE);
    cudaFuncSetAttribute(bilinear_mma, cudaFuncAttributeMaxDynamicSharedMemorySize, 2 * BL_STAGE);

    {
        int n4 = MTOT * D / 4;
        split_x_kernel<<<(n4 + 255) / 256, 256>>>(x);
    }
    {
        pack_w_kernel<<<(D * D + 255) / 256, 256>>>(W);
    }
    {
        dim3 grid(D / 64, (MTOT + 127) / 128);            // (5, 129)
        xw_mma<<<grid, 256, 2 * XW_STAGE>>>();
    }
    {
        dim3 grid((L + 255) / 256, (L + 127) / 128, NB);  // (9, 17, 8)
        bilinear_mma<<<grid, 256, 2 * BL_STAGE>>>(bias, out);
    }
}

// round 5
// speedup vs baseline: 2.3585x; 1.3997x over previous
#include <cuda_runtime.h>
#include <cuda_bf16.h>
#include <cstdint>

#define NB 8
#define L  2050
#define D  320
#define KP 960              // packed K = 3*D
#define MTOT (NB * L)

// ---------------------------------------------------------------------------
// Packed bf16 operands:
//   xpack row = [x_hi | x_lo | x_hi],  ypack row = [y_hi | y_hi | y_lo]
//   wpack row e = [Wh(:,e) | Wh(:,e) | Wl(:,e)]
// dot(ypack_i, xpack_j) = yh·xh + yh·xl + yl·xh  (compensated bf16 product)
// ---------------------------------------------------------------------------
__device__ __align__(1024) __nv_bfloat16 g_xpack[MTOT * KP];
__device__ __align__(1024) __nv_bfloat16 g_ypack[MTOT * KP];
__device__ __align__(1024) __nv_bfloat16 g_wpack[D * KP];

__device__ __forceinline__ uint32_t smem_u32(const void* p) {
    uint32_t a;
    asm("{ .reg .u64 t; cvta.to.shared.u64 t, %1; cvt.u32.u64 %0, t; }" : "=r"(a) : "l"(p));
    return a;
}
__device__ __forceinline__ void cp_async16(uint32_t dst, const void* src) {
    asm volatile("cp.async.cg.shared.global [%0], [%1], 16;" :: "r"(dst), "l"(src) : "memory");
}
__device__ __forceinline__ void cp_commit() {
    asm volatile("cp.async.commit_group;" ::: "memory");
}
template <int N>
__device__ __forceinline__ void cp_wait() {
    asm volatile("cp.async.wait_group %0;" :: "n"(N) : "memory");
}
__device__ __forceinline__ void ldmatrix_x4(uint32_t& r0, uint32_t& r1, uint32_t& r2, uint32_t& r3,
                                            uint32_t addr) {
    asm volatile("ldmatrix.sync.aligned.m8n8.x4.shared.b16 {%0,%1,%2,%3}, [%4];"
                 : "=r"(r0), "=r"(r1), "=r"(r2), "=r"(r3) : "r"(addr));
}
__device__ __forceinline__ void mma16816(float* c, const uint32_t* a, uint32_t b0, uint32_t b1) {
    asm volatile("mma.sync.aligned.m16n8k16.row.col.f32.bf16.bf16.f32 "
                 "{%0,%1,%2,%3}, {%4,%5,%6,%7}, {%8,%9}, {%0,%1,%2,%3};"
                 : "+f"(c[0]), "+f"(c[1]), "+f"(c[2]), "+f"(c[3])
                 : "r"(a[0]), "r"(a[1]), "r"(a[2]), "r"(a[3]), "r"(b0), "r"(b1));
}
__device__ __forceinline__ uint32_t sw128(uint32_t off) {
    return off ^ ((off >> 3) & 0x70);
}
__device__ __forceinline__ uint32_t pack_bf2(__nv_bfloat16 a, __nv_bfloat16 b) {
    return (uint32_t)__bfloat16_as_ushort(a) | ((uint32_t)__bfloat16_as_ushort(b) << 16);
}

// ---------------------------------------------------------------------------
// Kernel 0: split x -> xpack [hi | lo | hi]
// ---------------------------------------------------------------------------
__global__ __launch_bounds__(256) void split_x_kernel(const float* __restrict__ X)
{
    const int N4 = MTOT * D / 4;
    int i4 = blockIdx.x * blockDim.x + threadIdx.x;
    if (i4 >= N4) return;
    float4 v = reinterpret_cast<const float4*>(X)[i4];
    float vv[4] = {v.x, v.y, v.z, v.w};
    __nv_bfloat16 h[4], l[4];
#pragma unroll
    for (int k = 0; k < 4; k++) {
        h[k] = __float2bfloat16(vv[k]);
        l[k] = __float2bfloat16(vv[k] - __bfloat162float(h[k]));
    }
    int row = (i4 * 4) / D;
    int col = (i4 * 4) % D;
    __nv_bfloat16* base = g_xpack + (size_t)row * KP;
    uint2 hv = make_uint2(pack_bf2(h[0], h[1]), pack_bf2(h[2], h[3]));
    uint2 lv = make_uint2(pack_bf2(l[0], l[1]), pack_bf2(l[2], l[3]));
    *reinterpret_cast<uint2*>(base + col)       = hv;
    *reinterpret_cast<uint2*>(base + 320 + col) = lv;
    *reinterpret_cast<uint2*>(base + 640 + col) = hv;
}

// ---------------------------------------------------------------------------
// Kernel 0b: pack W -> wpack
// ---------------------------------------------------------------------------
__global__ __launch_bounds__(256) void pack_w_kernel(const float* __restrict__ W)
{
    int i = blockIdx.x * blockDim.x + threadIdx.x;
    if (i >= D * D) return;
    int d = i / D, e = i % D;
    float w = W[(size_t)d * D + e];
    __nv_bfloat16 h = __float2bfloat16(w);
    __nv_bfloat16 l = __float2bfloat16(w - __bfloat162float(h));
    __nv_bfloat16* base = g_wpack + (size_t)e * KP;
    base[d]       = h;
    base[320 + d] = h;
    base[640 + d] = l;
}

// ---------------------------------------------------------------------------
// Kernel 1: y = x @ W via bf16 split mma (NT: A=xpack, B=wpack).
// CTA 128x64, 8 warps (4m x 2n), warp 32x32. Epilogue -> ypack [hi|hi|lo].
// ---------------------------------------------------------------------------
#define XW_STAGE ((128 + 64) * 128)              // 24576 B

__global__ __launch_bounds__(256) void xw_mma(void)
{
    extern __shared__ char smem[];
    const uint32_t sbase = smem_u32(smem);
    const int tid  = threadIdx.x;
    const int wid  = tid >> 5;
    const int lane = tid & 31;

    const int row0 = blockIdx.y * 128;
    const int col0 = blockIdx.x * 64;
    const int wm = (wid >> 1) * 32;
    const int wn = (wid & 1) * 32;

    float acc[2][4][4];
#pragma unroll
    for (int mi = 0; mi < 2; mi++)
#pragma unroll
        for (int ni = 0; ni < 4; ni++)
#pragma unroll
            for (int e = 0; e < 4; e++) acc[mi][ni][e] = 0.0f;

    auto load_tiles = [&](int kb, int s) {
        const uint32_t stage = sbase + (uint32_t)s * XW_STAGE;
        const int koff = kb * 64;
#pragma unroll
        for (int it = tid; it < 1024; it += 256) {
            int r = it >> 3, c = it & 7;
            uint32_t dst = stage + sw128((uint32_t)(r * 128 + c * 16));
            int grow = row0 + r;
            if (grow < MTOT) cp_async16(dst, g_xpack + (size_t)grow * KP + koff + c * 8);
            else *reinterpret_cast<uint4*>(smem + (dst - sbase)) = make_uint4(0, 0, 0, 0);
        }
#pragma unroll
        for (int it = tid; it < 512; it += 256) {
            int r = it >> 3, c = it & 7;
            uint32_t dst = stage + 16384 + sw128((uint32_t)(r * 128 + c * 16));
            cp_async16(dst, g_wpack + (size_t)(col0 + r) * KP + koff + c * 8);
        }
    };

    load_tiles(0, 0);
    cp_commit();

    for (int kb = 0; kb < KP / 64; kb++) {
        const int s = kb & 1;
        cp_wait<0>();
        __syncthreads();
        if (kb + 1 < KP / 64) { load_tiles(kb + 1, s ^ 1); cp_commit(); }

        const uint32_t sA = sbase + (uint32_t)s * XW_STAGE;
        const uint32_t sB = sA + 16384;
#pragma unroll
        for (int ks = 0; ks < 4; ks++) {
            uint32_t a[2][4];
#pragma unroll
            for (int mi = 0; mi < 2; mi++) {
                int r = wm + mi * 16 + (lane & 7) + ((lane >> 3) & 1) * 8;
                int c = ks * 2 + (lane >> 4);
                ldmatrix_x4(a[mi][0], a[mi][1], a[mi][2], a[mi][3],
                            sA + sw128((uint32_t)(r * 128 + c * 16)));
            }
#pragma unroll
            for (int nj = 0; nj < 2; nj++) {
                uint32_t bf[4];
                int n = wn + nj * 16 + (lane & 7) + (lane >> 4) * 8;
                int c = ks * 2 + ((lane >> 3) & 1);
                ldmatrix_x4(bf[0], bf[1], bf[2], bf[3],
                            sB + sw128((uint32_t)(n * 128 + c * 16)));
#pragma unroll
                for (int mi = 0; mi < 2; mi++) {
                    mma16816(acc[mi][nj * 2],     a[mi], bf[0], bf[1]);
                    mma16816(acc[mi][nj * 2 + 1], a[mi], bf[2], bf[3]);
                }
            }
        }
        __syncthreads();
    }

#pragma unroll
    for (int mi = 0; mi < 2; mi++) {
        int r0 = row0 + wm + mi * 16 + (lane >> 2);
#pragma unroll
        for (int ni = 0; ni < 4; ni++) {
            int col = col0 + wn + ni * 8 + (lane & 3) * 2;
#pragma unroll
            for (int h = 0; h < 2; h++) {
                int row = r0 + h * 8;
                if (row >= MTOT) continue;
                float v0 = acc[mi][ni][h * 2];
                float v1 = acc[mi][ni][h * 2 + 1];
                __nv_bfloat16 h0 = __float2bfloat16(v0);
                __nv_bfloat16 h1 = __float2bfloat16(v1);
                __nv_bfloat16 l0 = __float2bfloat16(v0 - __bfloat162float(h0));
                __nv_bfloat16 l1 = __float2bfloat16(v1 - __bfloat162float(h1));
                uint32_t hp = pack_bf2(h0, h1);
                uint32_t lp = pack_bf2(l0, l1);
                __nv_bfloat16* base = g_ypack + (size_t)row * KP;
                *reinterpret_cast<uint32_t*>(base + col)       = hp;
                *reinterpret_cast<uint32_t*>(base + 320 + col) = hp;
                *reinterpret_cast<uint32_t*>(base + 640 + col) = lp;
            }
        }
    }
}

// ---------------------------------------------------------------------------
// Kernel 2: out = sigmoid(ypack · xpack^T + bias).
// CTA 128x128, 8 warps (2m x 4n), warp 64x32 (regs ~127 -> 2 CTAs/SM).
// 3-stage cp.async pipeline, wait_group 1: one full kb always in flight.
// ---------------------------------------------------------------------------
#define BL_STAGE ((128 + 128) * 128)             // 32768 B per stage
#define BL_NSTAGE 3
#define NKB (KP / 64)                            // 15

__global__ __launch_bounds__(256, 2) void bilinear_mma(const float* __restrict__ bias,
                                                       float* __restrict__ out)
{
    extern __shared__ char smem[];
    const uint32_t sbase = smem_u32(smem);
    const int tid  = threadIdx.x;
    const int wid  = tid >> 5;
    const int lane = tid & 31;

    const int b    = blockIdx.z;
    const int row0 = blockIdx.y * 128;
    const int col0 = blockIdx.x * 128;

    const __nv_bfloat16* Ag = g_ypack + (size_t)b * L * KP;
    const __nv_bfloat16* Bg = g_xpack + (size_t)b * L * KP;

    const int wm = (wid >> 2) * 64;      // 2 m-positions
    const int wn = (wid & 3) * 32;       // 4 n-positions

    float acc[4][4][4];
#pragma unroll
    for (int mi = 0; mi < 4; mi++)
#pragma unroll
        for (int ni = 0; ni < 4; ni++)
#pragma unroll
            for (int e = 0; e < 4; e++) acc[mi][ni][e] = 0.0f;

    auto load_tiles = [&](int kb, int s) {
        const uint32_t stage = sbase + (uint32_t)s * BL_STAGE;
        const int koff = kb * 64;
#pragma unroll
        for (int it = tid; it < 1024; it += 256) {       // A: 128 rows x 8
            int r = it >> 3, c = it & 7;
            uint32_t dst = stage + sw128((uint32_t)(r * 128 + c * 16));
            int grow = row0 + r;
            if (grow < L) cp_async16(dst, Ag + (size_t)grow * KP + koff + c * 8);
            else *reinterpret_cast<uint4*>(smem + (dst - sbase)) = make_uint4(0, 0, 0, 0);
        }
#pragma unroll
        for (int it = tid; it < 1024; it += 256) {       // B: 128 rows x 8
            int r = it >> 3, c = it & 7;
            uint32_t dst = stage + 16384 + sw128((uint32_t)(r * 128 + c * 16));
            int grow = col0 + r;
            if (grow < L) cp_async16(dst, Bg + (size_t)grow * KP + koff + c * 8);
            else *reinterpret_cast<uint4*>(smem + (dst - sbase)) = make_uint4(0, 0, 0, 0);
        }
    };

    // Prologue: stages for kb=0,1
    load_tiles(0, 0);
    cp_commit();
    load_tiles(1, 1);
    cp_commit();

    for (int kb = 0; kb < NKB; kb++) {
        const int s = kb % BL_NSTAGE;
        cp_wait<1>();                  // kb's group done; kb+1 may be in flight
        __syncthreads();               // all threads' copies visible; prev compute done
        if (kb + 2 < NKB) load_tiles(kb + 2, (kb + 2) % BL_NSTAGE);
        cp_commit();                   // commit (possibly empty) to keep group count in sync

        const uint32_t sA = sbase + (uint32_t)s * BL_STAGE;
        const uint32_t sB = sA + 16384;

#pragma unroll
        for (int ks = 0; ks < 4; ks++) {
            uint32_t a[4][4];
#pragma unroll
            for (int mi = 0; mi < 4; mi++) {
                int r = wm + mi * 16 + (lane & 7) + ((lane >> 3) & 1) * 8;
                int c = ks * 2 + (lane >> 4);
                ldmatrix_x4(a[mi][0], a[mi][1], a[mi][2], a[mi][3],
                            sA + sw128((uint32_t)(r * 128 + c * 16)));
            }
#pragma unroll
            for (int nj = 0; nj < 2; nj++) {
                uint32_t bf[4];
                int n = wn + nj * 16 + (lane & 7) + (lane >> 4) * 8;
                int c = ks * 2 + ((lane >> 3) & 1);
                ldmatrix_x4(bf[0], bf[1], bf[2], bf[3],
                            sB + sw128((uint32_t)(n * 128 + c * 16)));
#pragma unroll
                for (int mi = 0; mi < 4; mi++) {
                    mma16816(acc[mi][nj * 2],     a[mi], bf[0], bf[1]);
                    mma16816(acc[mi][nj * 2 + 1], a[mi], bf[2], bf[3]);
                }
            }
        }
    }

    // Epilogue: bias + sigmoid
    const float biasv = bias[0];
    float* obase = out + (size_t)b * L * L;
#pragma unroll
    for (int mi = 0; mi < 4; mi++) {
        int r0 = row0 + wm + mi * 16 + (lane >> 2);
#pragma unroll
        for (int ni = 0; ni < 4; ni++) {
            int col = col0 + wn + ni * 8 + (lane & 3) * 2;
            if (col >= L) continue;
#pragma unroll
            for (int h = 0; h < 2; h++) {
                int row = r0 + h * 8;
                if (row >= L) continue;
                float z0 = acc[mi][ni][h * 2]     + biasv;
                float z1 = acc[mi][ni][h * 2 + 1] + biasv;
                float2 o;
                o.x = 1.0f / (1.0f + __expf(-z0));
                o.y = 1.0f / (1.0f + __expf(-z1));
                *reinterpret_cast<float2*>(&obase[(size_t)row * L + col]) = o;
            }
        }
    }
}

// ---------------------------------------------------------------------------
extern "C" void kernel_launch(void* const* d_in, const int* in_sizes, int n_in,
                              void* d_out, int out_size)
{
    const float* x    = (const float*)d_in[0];   // (8, 2050, 320)
    const float* W    = (const float*)d_in[1];   // (320, 320)
    const float* bias = (const float*)d_in[2];   // (1,)
    float* out = (float*)d_out;                  // (8, 2050, 2050)

    cudaFuncSetAttribute(xw_mma, cudaFuncAttributeMaxDynamicSharedMemorySize, 2 * XW_STAGE);
    cudaFuncSetAttribute(bilinear_mma, cudaFuncAttributeMaxDynamicSharedMemorySize,
                         BL_NSTAGE * BL_STAGE);

    {
        int n4 = MTOT * D / 4;
        split_x_kernel<<<(n4 + 255) / 256, 256>>>(x);
    }
    {
        pack_w_kernel<<<(D * D + 255) / 256, 256>>>(W);
    }
    {
        dim3 grid(D / 64, (MTOT + 127) / 128);            // (5, 129)
        xw_mma<<<grid, 256, 2 * XW_STAGE>>>();
    }
    {
        dim3 grid((L + 127) / 128, (L + 127) / 128, NB);  // (17,17,8)
        bilinear_mma<<<grid, 256, BL_NSTAGE * BL_STAGE>>>(bias, out);
    }
}

// round 6
// speedup vs baseline: 2.5338x; 1.0743x over previous
#include <cuda_runtime.h>
#include <cuda_bf16.h>
#include <cstdint>

#define NB 8
#define L  2050
#define D  320
#define KU 640              // unique packed K = 2*D  (hi | lo)
#define MTOT (NB * L)

// ---------------------------------------------------------------------------
// Compact packed bf16 operands (unique data only):
//   xp row = [x_hi(320) | x_lo(320)],  yp row = [y_hi(320) | y_lo(320)]
//   wp row e = [Wh(:,e)(320) | Wl(:,e)(320)]
// Compensated product realized by FRAGMENT REUSE at mma level:
//   acc += ah*bh + ah*bl + al*bh   (al overwrites ah's registers)
// ---------------------------------------------------------------------------
__device__ __align__(1024) __nv_bfloat16 g_xp[MTOT * KU];
__device__ __align__(1024) __nv_bfloat16 g_yp[MTOT * KU];
__device__ __align__(1024) __nv_bfloat16 g_wp[D * KU];

__device__ __forceinline__ uint32_t smem_u32(const void* p) {
    uint32_t a;
    asm("{ .reg .u64 t; cvta.to.shared.u64 t, %1; cvt.u32.u64 %0, t; }" : "=r"(a) : "l"(p));
    return a;
}
__device__ __forceinline__ void cp_async16(uint32_t dst, const void* src) {
    asm volatile("cp.async.cg.shared.global [%0], [%1], 16;" :: "r"(dst), "l"(src) : "memory");
}
__device__ __forceinline__ void cp_commit() {
    asm volatile("cp.async.commit_group;" ::: "memory");
}
template <int N>
__device__ __forceinline__ void cp_wait() {
    asm volatile("cp.async.wait_group %0;" :: "n"(N) : "memory");
}
__device__ __forceinline__ void ldmatrix_x4(uint32_t* r, uint32_t addr) {
    asm volatile("ldmatrix.sync.aligned.m8n8.x4.shared.b16 {%0,%1,%2,%3}, [%4];"
                 : "=r"(r[0]), "=r"(r[1]), "=r"(r[2]), "=r"(r[3]) : "r"(addr));
}
__device__ __forceinline__ void mma16816(float* c, const uint32_t* a, uint32_t b0, uint32_t b1) {
    asm volatile("mma.sync.aligned.m16n8k16.row.col.f32.bf16.bf16.f32 "
                 "{%0,%1,%2,%3}, {%4,%5,%6,%7}, {%8,%9}, {%0,%1,%2,%3};"
                 : "+f"(c[0]), "+f"(c[1]), "+f"(c[2]), "+f"(c[3])
                 : "r"(a[0]), "r"(a[1]), "r"(a[2]), "r"(a[3]), "r"(b0), "r"(b1));
}
__device__ __forceinline__ uint32_t sw128(uint32_t off) {
    return off ^ ((off >> 3) & 0x70);
}
__device__ __forceinline__ uint32_t pack_bf2(__nv_bfloat16 a, __nv_bfloat16 b) {
    return (uint32_t)__bfloat16_as_ushort(a) | ((uint32_t)__bfloat16_as_ushort(b) << 16);
}

// ---------------------------------------------------------------------------
// Kernel 0: split x -> xp [hi | lo]
// ---------------------------------------------------------------------------
__global__ __launch_bounds__(256) void split_x_kernel(const float* __restrict__ X)
{
    const int N4 = MTOT * D / 4;
    int i4 = blockIdx.x * blockDim.x + threadIdx.x;
    if (i4 >= N4) return;
    float4 v = reinterpret_cast<const float4*>(X)[i4];
    float vv[4] = {v.x, v.y, v.z, v.w};
    __nv_bfloat16 h[4], l[4];
#pragma unroll
    for (int k = 0; k < 4; k++) {
        h[k] = __float2bfloat16(vv[k]);
        l[k] = __float2bfloat16(vv[k] - __bfloat162float(h[k]));
    }
    int row = (i4 * 4) / D;
    int col = (i4 * 4) % D;
    __nv_bfloat16* base = g_xp + (size_t)row * KU;
    *reinterpret_cast<uint2*>(base + col)       = make_uint2(pack_bf2(h[0], h[1]), pack_bf2(h[2], h[3]));
    *reinterpret_cast<uint2*>(base + 320 + col) = make_uint2(pack_bf2(l[0], l[1]), pack_bf2(l[2], l[3]));
}

// ---------------------------------------------------------------------------
// Kernel 0b: pack W -> wp; row e = [Wh(:,e) | Wl(:,e)]
// ---------------------------------------------------------------------------
__global__ __launch_bounds__(256) void pack_w_kernel(const float* __restrict__ W)
{
    int i = blockIdx.x * blockDim.x + threadIdx.x;
    if (i >= D * D) return;
    int d = i / D, e = i % D;
    float w = W[(size_t)d * D + e];
    __nv_bfloat16 h = __float2bfloat16(w);
    __nv_bfloat16 l = __float2bfloat16(w - __bfloat162float(h));
    __nv_bfloat16* base = g_wp + (size_t)e * KU;
    base[d]       = h;
    base[320 + d] = l;
}

// ---------------------------------------------------------------------------
// Kernel 1: y = x @ W via compensated bf16 mma (NT: A=xp, B=wp).
// CTA 128x64, 8 warps (4m x 2n), warp 32x32. Unique K=320, 10 kb of 32.
// smem row = [h(32) | l(32)] bf16 = 128B, SW128.
// Epilogue -> yp [hi | lo].
// ---------------------------------------------------------------------------
#define XW_STAGE ((128 + 64) * 128)              // 24576 B
#define XW_NKB 10

__global__ __launch_bounds__(256) void xw_mma(void)
{
    extern __shared__ char smem[];
    const uint32_t sbase = smem_u32(smem);
    const int tid  = threadIdx.x;
    const int wid  = tid >> 5;
    const int lane = tid & 31;

    const int row0 = blockIdx.y * 128;
    const int col0 = blockIdx.x * 64;
    const int wm = (wid >> 1) * 32;
    const int wn = (wid & 1) * 32;

    float acc[2][4][4];
#pragma unroll
    for (int mi = 0; mi < 2; mi++)
#pragma unroll
        for (int ni = 0; ni < 4; ni++)
#pragma unroll
            for (int e = 0; e < 4; e++) acc[mi][ni][e] = 0.0f;

    auto load_tiles = [&](int kb, int s) {
        const uint32_t stage = sbase + (uint32_t)s * XW_STAGE;
        const int koff = kb * 32;
#pragma unroll
        for (int it = tid; it < 1024; it += 256) {       // A: 128 rows x 8 chunks
            int r = it >> 3, c = it & 7;
            int scol = koff + (c & 3) * 8 + ((c >> 2) * 320);
            uint32_t dst = stage + sw128((uint32_t)(r * 128 + c * 16));
            int grow = row0 + r;
            if (grow < MTOT) cp_async16(dst, g_xp + (size_t)grow * KU + scol);
            else *reinterpret_cast<uint4*>(smem + (dst - sbase)) = make_uint4(0, 0, 0, 0);
        }
#pragma unroll
        for (int it = tid; it < 512; it += 256) {        // B: 64 rows x 8
            int r = it >> 3, c = it & 7;
            int scol = koff + (c & 3) * 8 + ((c >> 2) * 320);
            uint32_t dst = stage + 16384 + sw128((uint32_t)(r * 128 + c * 16));
            cp_async16(dst, g_wp + (size_t)(col0 + r) * KU + scol);
        }
    };

    load_tiles(0, 0);
    cp_commit();

    for (int kb = 0; kb < XW_NKB; kb++) {
        const int s = kb & 1;
        cp_wait<0>();
        __syncthreads();
        if (kb + 1 < XW_NKB) { load_tiles(kb + 1, s ^ 1); cp_commit(); }

        const uint32_t sA = sbase + (uint32_t)s * XW_STAGE;
        const uint32_t sB = sA + 16384;
#pragma unroll
        for (int ks = 0; ks < 2; ks++) {
            uint32_t a[2][4], bh[2][4], bl[2][4];
            const int ca = ks * 2 + (lane >> 4);          // A col unit (hi)
            const int cb = ks * 2 + ((lane >> 3) & 1);    // B col unit (hi)
#pragma unroll
            for (int mi = 0; mi < 2; mi++) {
                int r = wm + mi * 16 + (lane & 7) + ((lane >> 3) & 1) * 8;
                ldmatrix_x4(a[mi], sA + sw128((uint32_t)(r * 128 + ca * 16)));
            }
#pragma unroll
            for (int nj = 0; nj < 2; nj++) {
                int n = wn + nj * 16 + (lane & 7) + (lane >> 4) * 8;
                ldmatrix_x4(bh[nj], sB + sw128((uint32_t)(n * 128 + cb * 16)));
                ldmatrix_x4(bl[nj], sB + sw128((uint32_t)(n * 128 + (cb + 4) * 16)));
            }
            // ah*bh + ah*bl
#pragma unroll
            for (int nj = 0; nj < 2; nj++)
#pragma unroll
                for (int mi = 0; mi < 2; mi++) {
                    mma16816(acc[mi][nj * 2],     a[mi], bh[nj][0], bh[nj][1]);
                    mma16816(acc[mi][nj * 2 + 1], a[mi], bh[nj][2], bh[nj][3]);
                    mma16816(acc[mi][nj * 2],     a[mi], bl[nj][0], bl[nj][1]);
                    mma16816(acc[mi][nj * 2 + 1], a[mi], bl[nj][2], bl[nj][3]);
                }
            // al (reuse a regs), al*bh
#pragma unroll
            for (int mi = 0; mi < 2; mi++) {
                int r = wm + mi * 16 + (lane & 7) + ((lane >> 3) & 1) * 8;
                ldmatrix_x4(a[mi], sA + sw128((uint32_t)(r * 128 + (ca + 4) * 16)));
            }
#pragma unroll
            for (int nj = 0; nj < 2; nj++)
#pragma unroll
                for (int mi = 0; mi < 2; mi++) {
                    mma16816(acc[mi][nj * 2],     a[mi], bh[nj][0], bh[nj][1]);
                    mma16816(acc[mi][nj * 2 + 1], a[mi], bh[nj][2], bh[nj][3]);
                }
        }
        __syncthreads();
    }

    // Epilogue: split y -> yp [hi | lo]
#pragma unroll
    for (int mi = 0; mi < 2; mi++) {
        int r0 = row0 + wm + mi * 16 + (lane >> 2);
#pragma unroll
        for (int ni = 0; ni < 4; ni++) {
            int col = col0 + wn + ni * 8 + (lane & 3) * 2;
#pragma unroll
            for (int h = 0; h < 2; h++) {
                int row = r0 + h * 8;
                if (row >= MTOT) continue;
                float v0 = acc[mi][ni][h * 2];
                float v1 = acc[mi][ni][h * 2 + 1];
                __nv_bfloat16 h0 = __float2bfloat16(v0);
                __nv_bfloat16 h1 = __float2bfloat16(v1);
                __nv_bfloat16 l0 = __float2bfloat16(v0 - __bfloat162float(h0));
                __nv_bfloat16 l1 = __float2bfloat16(v1 - __bfloat162float(h1));
                __nv_bfloat16* base = g_yp + (size_t)row * KU;
                *reinterpret_cast<uint32_t*>(base + col)       = pack_bf2(h0, h1);
                *reinterpret_cast<uint32_t*>(base + 320 + col) = pack_bf2(l0, l1);
            }
        }
    }
}

// ---------------------------------------------------------------------------
// Kernel 2: out = sigmoid(yp · xp^T + bias).  Unique K=640, 10 kb of 32.
// CTA 128x128, 8 warps (2m x 4n), warp 64x32, 2 CTAs/SM.
// 3-stage cp.async pipeline (wait_group 1). smem row = [h|l] 128B SW128.
// Per ks: 12 ldmatrix, 48 mma (ratio 4:1).
// ---------------------------------------------------------------------------
#define BL_STAGE ((128 + 128) * 128)             // 32768 B per stage
#define BL_NSTAGE 3
#define BL_NKB 10

__global__ __launch_bounds__(256, 2) void bilinear_mma(const float* __restrict__ bias,
                                                       float* __restrict__ out)
{
    extern __shared__ char smem[];
    const uint32_t sbase = smem_u32(smem);
    const int tid  = threadIdx.x;
    const int wid  = tid >> 5;
    const int lane = tid & 31;

    const int b    = blockIdx.z;
    const int row0 = blockIdx.y * 128;
    const int col0 = blockIdx.x * 128;

    const __nv_bfloat16* Ag = g_yp + (size_t)b * L * KU;
    const __nv_bfloat16* Bg = g_xp + (size_t)b * L * KU;

    const int wm = (wid >> 2) * 64;      // 2 m-positions
    const int wn = (wid & 3) * 32;       // 4 n-positions

    float acc[4][4][4];
#pragma unroll
    for (int mi = 0; mi < 4; mi++)
#pragma unroll
        for (int ni = 0; ni < 4; ni++)
#pragma unroll
            for (int e = 0; e < 4; e++) acc[mi][ni][e] = 0.0f;

    auto load_tiles = [&](int kb, int s) {
        const uint32_t stage = sbase + (uint32_t)s * BL_STAGE;
        const int koff = kb * 32;
#pragma unroll
        for (int it = tid; it < 1024; it += 256) {       // A: 128 rows x 8 chunks
            int r = it >> 3, c = it & 7;
            int scol = koff + (c & 3) * 8 + ((c >> 2) * 320);
            uint32_t dst = stage + sw128((uint32_t)(r * 128 + c * 16));
            int grow = row0 + r;
            if (grow < L) cp_async16(dst, Ag + (size_t)grow * KU + scol);
            else *reinterpret_cast<uint4*>(smem + (dst - sbase)) = make_uint4(0, 0, 0, 0);
        }
#pragma unroll
        for (int it = tid; it < 1024; it += 256) {       // B: 128 rows x 8 chunks
            int r = it >> 3, c = it & 7;
            int scol = koff + (c & 3) * 8 + ((c >> 2) * 320);
            uint32_t dst = stage + 16384 + sw128((uint32_t)(r * 128 + c * 16));
            int grow = col0 + r;
            if (grow < L) cp_async16(dst, Bg + (size_t)grow * KU + scol);
            else *reinterpret_cast<uint4*>(smem + (dst - sbase)) = make_uint4(0, 0, 0, 0);
        }
    };

    load_tiles(0, 0);
    cp_commit();
    load_tiles(1, 1);
    cp_commit();

    for (int kb = 0; kb < BL_NKB; kb++) {
        const int s = kb % BL_NSTAGE;
        cp_wait<1>();
        __syncthreads();
        if (kb + 2 < BL_NKB) load_tiles(kb + 2, (kb + 2) % BL_NSTAGE);
        cp_commit();

        const uint32_t sA = sbase + (uint32_t)s * BL_STAGE;
        const uint32_t sB = sA + 16384;

#pragma unroll
        for (int ks = 0; ks < 2; ks++) {
            uint32_t a[4][4], bh[2][4], bl[2][4];
            const int ca = ks * 2 + (lane >> 4);
            const int cb = ks * 2 + ((lane >> 3) & 1);
#pragma unroll
            for (int mi = 0; mi < 4; mi++) {
                int r = wm + mi * 16 + (lane & 7) + ((lane >> 3) & 1) * 8;
                ldmatrix_x4(a[mi], sA + sw128((uint32_t)(r * 128 + ca * 16)));
            }
#pragma unroll
            for (int nj = 0; nj < 2; nj++) {
                int n = wn + nj * 16 + (lane & 7) + (lane >> 4) * 8;
                ldmatrix_x4(bh[nj], sB + sw128((uint32_t)(n * 128 + cb * 16)));
                ldmatrix_x4(bl[nj], sB + sw128((uint32_t)(n * 128 + (cb + 4) * 16)));
            }
            // ah*bh + ah*bl
#pragma unroll
            for (int nj = 0; nj < 2; nj++)
#pragma unroll
                for (int mi = 0; mi < 4; mi++) {
                    mma16816(acc[mi][nj * 2],     a[mi], bh[nj][0], bh[nj][1]);
                    mma16816(acc[mi][nj * 2 + 1], a[mi], bh[nj][2], bh[nj][3]);
                    mma16816(acc[mi][nj * 2],     a[mi], bl[nj][0], bl[nj][1]);
                    mma16816(acc[mi][nj * 2 + 1], a[mi], bl[nj][2], bl[nj][3]);
                }
            // al (reuse a regs), al*bh
#pragma unroll
            for (int mi = 0; mi < 4; mi++) {
                int r = wm + mi * 16 + (lane & 7) + ((lane >> 3) & 1) * 8;
                ldmatrix_x4(a[mi], sA + sw128((uint32_t)(r * 128 + (ca + 4) * 16)));
            }
#pragma unroll
            for (int nj = 0; nj < 2; nj++)
#pragma unroll
                for (int mi = 0; mi < 4; mi++) {
                    mma16816(acc[mi][nj * 2],     a[mi], bh[nj][0], bh[nj][1]);
                    mma16816(acc[mi][nj * 2 + 1], a[mi], bh[nj][2], bh[nj][3]);
                }
        }
    }

    // Epilogue: bias + sigmoid
    const float biasv = bias[0];
    float* obase = out + (size_t)b * L * L;
#pragma unroll
    for (int mi = 0; mi < 4; mi++) {
        int r0 = row0 + wm + mi * 16 + (lane >> 2);
#pragma unroll
        for (int ni = 0; ni < 4; ni++) {
            int col = col0 + wn + ni * 8 + (lane & 3) * 2;
            if (col >= L) continue;
#pragma unroll
            for (int h = 0; h < 2; h++) {
                int row = r0 + h * 8;
                if (row >= L) continue;
                float z0 = acc[mi][ni][h * 2]     + biasv;
                float z1 = acc[mi][ni][h * 2 + 1] + biasv;
                float2 o;
                o.x = 1.0f / (1.0f + __expf(-z0));
                o.y = 1.0f / (1.0f + __expf(-z1));
                *reinterpret_cast<float2*>(&obase[(size_t)row * L + col]) = o;
            }
        }
    }
}

// ---------------------------------------------------------------------------
extern "C" void kernel_launch(void* const* d_in, const int* in_sizes, int n_in,
                              void* d_out, int out_size)
{
    const float* x    = (const float*)d_in[0];   // (8, 2050, 320)
    const float* W    = (const float*)d_in[1];   // (320, 320)
    const float* bias = (const float*)d_in[2];   // (1,)
    float* out = (float*)d_out;                  // (8, 2050, 2050)

    cudaFuncSetAttribute(xw_mma, cudaFuncAttributeMaxDynamicSharedMemorySize, 2 * XW_STAGE);
    cudaFuncSetAttribute(bilinear_mma, cudaFuncAttributeMaxDynamicSharedMemorySize,
                         BL_NSTAGE * BL_STAGE);

    {
        int n4 = MTOT * D / 4;
        split_x_kernel<<<(n4 + 255) / 256, 256>>>(x);
    }
    {
        pack_w_kernel<<<(D * D + 255) / 256, 256>>>(W);
    }
    {
        dim3 grid(D / 64, (MTOT + 127) / 128);            // (5, 129)
        xw_mma<<<grid, 256, 2 * XW_STAGE>>>();
    }
    {
        dim3 grid((L + 127) / 128, (L + 127) / 128, NB);  // (17,17,8)
        bilinear_mma<<<grid, 256, BL_NSTAGE * BL_STAGE>>>(bias, out);
    }
}

// round 7
// speedup vs baseline: 2.6699x; 1.0537x over previous
#include <cuda_runtime.h>
#include <cuda_bf16.h>
#include <cstdint>

#define NB 8
#define L  2050
#define D  320
#define KU 640              // unique packed K = 2*D  (hi | lo)
#define MTOT (NB * L)

// ---------------------------------------------------------------------------
// Compact packed bf16 operands (unique data only):
//   xp row = [x_hi(320) | x_lo(320)],  yp row = [y_hi(320) | y_lo(320)]
//   wp row e = [Wh(:,e)(320) | Wl(:,e)(320)]
// Compensated product by fragment reuse: acc += ah*bh + ah*bl + al*bh
// ---------------------------------------------------------------------------
__device__ __align__(1024) __nv_bfloat16 g_xp[MTOT * KU];
__device__ __align__(1024) __nv_bfloat16 g_yp[MTOT * KU];
__device__ __align__(1024) __nv_bfloat16 g_wp[D * KU];

__device__ __forceinline__ uint32_t smem_u32(const void* p) {
    uint32_t a;
    asm("{ .reg .u64 t; cvta.to.shared.u64 t, %1; cvt.u32.u64 %0, t; }" : "=r"(a) : "l"(p));
    return a;
}
__device__ __forceinline__ void cp_async16(uint32_t dst, const void* src) {
    asm volatile("cp.async.cg.shared.global [%0], [%1], 16;" :: "r"(dst), "l"(src) : "memory");
}
__device__ __forceinline__ void cp_commit() {
    asm volatile("cp.async.commit_group;" ::: "memory");
}
template <int N>
__device__ __forceinline__ void cp_wait() {
    asm volatile("cp.async.wait_group %0;" :: "n"(N) : "memory");
}
__device__ __forceinline__ void ldmatrix_x4(uint32_t* r, uint32_t addr) {
    asm volatile("ldmatrix.sync.aligned.m8n8.x4.shared.b16 {%0,%1,%2,%3}, [%4];"
                 : "=r"(r[0]), "=r"(r[1]), "=r"(r[2]), "=r"(r[3]) : "r"(addr));
}
__device__ __forceinline__ void mma16816(float* c, const uint32_t* a, uint32_t b0, uint32_t b1) {
    asm volatile("mma.sync.aligned.m16n8k16.row.col.f32.bf16.bf16.f32 "
                 "{%0,%1,%2,%3}, {%4,%5,%6,%7}, {%8,%9}, {%0,%1,%2,%3};"
                 : "+f"(c[0]), "+f"(c[1]), "+f"(c[2]), "+f"(c[3])
                 : "r"(a[0]), "r"(a[1]), "r"(a[2]), "r"(a[3]), "r"(b0), "r"(b1));
}
__device__ __forceinline__ uint32_t sw128(uint32_t off) {
    return off ^ ((off >> 3) & 0x70);
}
__device__ __forceinline__ uint32_t pack_bf2(__nv_bfloat16 a, __nv_bfloat16 b) {
    return (uint32_t)__bfloat16_as_ushort(a) | ((uint32_t)__bfloat16_as_ushort(b) << 16);
}
// sigmoid(z) = 0.5*tanh(0.5*z) + 0.5, single MUFU
__device__ __forceinline__ float fast_sigmoid_half(float zh) {  // zh = 0.5*z already
    float t;
    asm("tanh.approx.f32 %0, %1;" : "=f"(t) : "f"(zh));
    return fmaf(t, 0.5f, 0.5f);
}

// ---------------------------------------------------------------------------
// Kernel 0 (fused): split x -> xp [hi|lo]  AND  pack W -> wp [Wh(:,e)|Wl(:,e)]
// ---------------------------------------------------------------------------
#define NX4 (MTOT * D / 4)
#define NW  (D * D)

__global__ __launch_bounds__(256) void split_pack_kernel(const float* __restrict__ X,
                                                         const float* __restrict__ W)
{
    int gi = blockIdx.x * blockDim.x + threadIdx.x;
    if (gi < NX4) {
        float4 v = reinterpret_cast<const float4*>(X)[gi];
        float vv[4] = {v.x, v.y, v.z, v.w};
        __nv_bfloat16 h[4], l[4];
#pragma unroll
        for (int k = 0; k < 4; k++) {
            h[k] = __float2bfloat16(vv[k]);
            l[k] = __float2bfloat16(vv[k] - __bfloat162float(h[k]));
        }
        int row = (gi * 4) / D;
        int col = (gi * 4) % D;
        __nv_bfloat16* base = g_xp + (size_t)row * KU;
        *reinterpret_cast<uint2*>(base + col)       = make_uint2(pack_bf2(h[0], h[1]), pack_bf2(h[2], h[3]));
        *reinterpret_cast<uint2*>(base + 320 + col) = make_uint2(pack_bf2(l[0], l[1]), pack_bf2(l[2], l[3]));
    } else {
        int i = gi - NX4;
        if (i >= NW) return;
        int d = i / D, e = i % D;
        float w = W[(size_t)d * D + e];
        __nv_bfloat16 h = __float2bfloat16(w);
        __nv_bfloat16 l = __float2bfloat16(w - __bfloat162float(h));
        __nv_bfloat16* base = g_wp + (size_t)e * KU;
        base[d]       = h;
        base[320 + d] = l;
    }
}

// ---------------------------------------------------------------------------
// Kernel 1: y = x @ W via compensated bf16 mma (NT: A=xp, B=wp).
// CTA 128x64, 8 warps (4m x 2n), warp 32x32. Epilogue -> yp [hi | lo].
// ---------------------------------------------------------------------------
#define XW_STAGE ((128 + 64) * 128)              // 24576 B
#define XW_NKB 10

__global__ __launch_bounds__(256) void xw_mma(void)
{
    extern __shared__ char smem[];
    const uint32_t sbase = smem_u32(smem);
    const int tid  = threadIdx.x;
    const int wid  = tid >> 5;
    const int lane = tid & 31;

    const int row0 = blockIdx.y * 128;
    const int col0 = blockIdx.x * 64;
    const int wm = (wid >> 1) * 32;
    const int wn = (wid & 1) * 32;

    float acc[2][4][4];
#pragma unroll
    for (int mi = 0; mi < 2; mi++)
#pragma unroll
        for (int ni = 0; ni < 4; ni++)
#pragma unroll
            for (int e = 0; e < 4; e++) acc[mi][ni][e] = 0.0f;

    auto load_tiles = [&](int kb, int s) {
        const uint32_t stage = sbase + (uint32_t)s * XW_STAGE;
        const int koff = kb * 32;
#pragma unroll
        for (int it = tid; it < 1024; it += 256) {
            int r = it >> 3, c = it & 7;
            int scol = koff + (c & 3) * 8 + ((c >> 2) * 320);
            uint32_t dst = stage + sw128((uint32_t)(r * 128 + c * 16));
            int grow = row0 + r;
            if (grow < MTOT) cp_async16(dst, g_xp + (size_t)grow * KU + scol);
            else *reinterpret_cast<uint4*>(smem + (dst - sbase)) = make_uint4(0, 0, 0, 0);
        }
#pragma unroll
        for (int it = tid; it < 512; it += 256) {
            int r = it >> 3, c = it & 7;
            int scol = koff + (c & 3) * 8 + ((c >> 2) * 320);
            uint32_t dst = stage + 16384 + sw128((uint32_t)(r * 128 + c * 16));
            cp_async16(dst, g_wp + (size_t)(col0 + r) * KU + scol);
        }
    };

    load_tiles(0, 0);
    cp_commit();

    for (int kb = 0; kb < XW_NKB; kb++) {
        const int s = kb & 1;
        cp_wait<0>();
        __syncthreads();
        if (kb + 1 < XW_NKB) { load_tiles(kb + 1, s ^ 1); cp_commit(); }

        const uint32_t sA = sbase + (uint32_t)s * XW_STAGE;
        const uint32_t sB = sA + 16384;
#pragma unroll
        for (int ks = 0; ks < 2; ks++) {
            uint32_t a[2][4], bh[2][4], bl[2][4];
            const int ca = ks * 2 + (lane >> 4);
            const int cb = ks * 2 + ((lane >> 3) & 1);
#pragma unroll
            for (int mi = 0; mi < 2; mi++) {
                int r = wm + mi * 16 + (lane & 7) + ((lane >> 3) & 1) * 8;
                ldmatrix_x4(a[mi], sA + sw128((uint32_t)(r * 128 + ca * 16)));
            }
#pragma unroll
            for (int nj = 0; nj < 2; nj++) {
                int n = wn + nj * 16 + (lane & 7) + (lane >> 4) * 8;
                ldmatrix_x4(bh[nj], sB + sw128((uint32_t)(n * 128 + cb * 16)));
                ldmatrix_x4(bl[nj], sB + sw128((uint32_t)(n * 128 + (cb + 4) * 16)));
            }
#pragma unroll
            for (int nj = 0; nj < 2; nj++)
#pragma unroll
                for (int mi = 0; mi < 2; mi++) {
                    mma16816(acc[mi][nj * 2],     a[mi], bh[nj][0], bh[nj][1]);
                    mma16816(acc[mi][nj * 2 + 1], a[mi], bh[nj][2], bh[nj][3]);
                    mma16816(acc[mi][nj * 2],     a[mi], bl[nj][0], bl[nj][1]);
                    mma16816(acc[mi][nj * 2 + 1], a[mi], bl[nj][2], bl[nj][3]);
                }
#pragma unroll
            for (int mi = 0; mi < 2; mi++) {
                int r = wm + mi * 16 + (lane & 7) + ((lane >> 3) & 1) * 8;
                ldmatrix_x4(a[mi], sA + sw128((uint32_t)(r * 128 + (ca + 4) * 16)));
            }
#pragma unroll
            for (int nj = 0; nj < 2; nj++)
#pragma unroll
                for (int mi = 0; mi < 2; mi++) {
                    mma16816(acc[mi][nj * 2],     a[mi], bh[nj][0], bh[nj][1]);
                    mma16816(acc[mi][nj * 2 + 1], a[mi], bh[nj][2], bh[nj][3]);
                }
        }
        __syncthreads();
    }

#pragma unroll
    for (int mi = 0; mi < 2; mi++) {
        int r0 = row0 + wm + mi * 16 + (lane >> 2);
#pragma unroll
        for (int ni = 0; ni < 4; ni++) {
            int col = col0 + wn + ni * 8 + (lane & 3) * 2;
#pragma unroll
            for (int h = 0; h < 2; h++) {
                int row = r0 + h * 8;
                if (row >= MTOT) continue;
                float v0 = acc[mi][ni][h * 2];
                float v1 = acc[mi][ni][h * 2 + 1];
                __nv_bfloat16 h0 = __float2bfloat16(v0);
                __nv_bfloat16 h1 = __float2bfloat16(v1);
                __nv_bfloat16 l0 = __float2bfloat16(v0 - __bfloat162float(h0));
                __nv_bfloat16 l1 = __float2bfloat16(v1 - __bfloat162float(h1));
                __nv_bfloat16* base = g_yp + (size_t)row * KU;
                *reinterpret_cast<uint32_t*>(base + col)       = pack_bf2(h0, h1);
                *reinterpret_cast<uint32_t*>(base + 320 + col) = pack_bf2(l0, l1);
            }
        }
    }
}

// ---------------------------------------------------------------------------
// Kernel 2: out = sigmoid(yp · xp^T + bias).  Unique K=640, 10 kb of 32.
// CTA 128x128, 8 warps (2m x 4n), warp 64x32, 2 CTAs/SM, 3-stage pipe.
// Epilogue: single-MUFU sigmoid via tanh.approx.
// ---------------------------------------------------------------------------
#define BL_STAGE ((128 + 128) * 128)             // 32768 B per stage
#define BL_NSTAGE 3
#define BL_NKB 10

__global__ __launch_bounds__(256, 2) void bilinear_mma(const float* __restrict__ bias,
                                                       float* __restrict__ out)
{
    extern __shared__ char smem[];
    const uint32_t sbase = smem_u32(smem);
    const int tid  = threadIdx.x;
    const int wid  = tid >> 5;
    const int lane = tid & 31;

    const int b    = blockIdx.z;
    const int row0 = blockIdx.y * 128;
    const int col0 = blockIdx.x * 128;

    const __nv_bfloat16* Ag = g_yp + (size_t)b * L * KU;
    const __nv_bfloat16* Bg = g_xp + (size_t)b * L * KU;

    const int wm = (wid >> 2) * 64;
    const int wn = (wid & 3) * 32;

    float acc[4][4][4];
#pragma unroll
    for (int mi = 0; mi < 4; mi++)
#pragma unroll
        for (int ni = 0; ni < 4; ni++)
#pragma unroll
            for (int e = 0; e < 4; e++) acc[mi][ni][e] = 0.0f;

    auto load_tiles = [&](int kb, int s) {
        const uint32_t stage = sbase + (uint32_t)s * BL_STAGE;
        const int koff = kb * 32;
#pragma unroll
        for (int it = tid; it < 1024; it += 256) {
            int r = it >> 3, c = it & 7;
            int scol = koff + (c & 3) * 8 + ((c >> 2) * 320);
            uint32_t dst = stage + sw128((uint32_t)(r * 128 + c * 16));
            int grow = row0 + r;
            if (grow < L) cp_async16(dst, Ag + (size_t)grow * KU + scol);
            else *reinterpret_cast<uint4*>(smem + (dst - sbase)) = make_uint4(0, 0, 0, 0);
        }
#pragma unroll
        for (int it = tid; it < 1024; it += 256) {
            int r = it >> 3, c = it & 7;
            int scol = koff + (c & 3) * 8 + ((c >> 2) * 320);
            uint32_t dst = stage + 16384 + sw128((uint32_t)(r * 128 + c * 16));
            int grow = col0 + r;
            if (grow < L) cp_async16(dst, Bg + (size_t)grow * KU + scol);
            else *reinterpret_cast<uint4*>(smem + (dst - sbase)) = make_uint4(0, 0, 0, 0);
        }
    };

    load_tiles(0, 0);
    cp_commit();
    load_tiles(1, 1);
    cp_commit();

    for (int kb = 0; kb < BL_NKB; kb++) {
        const int s = kb % BL_NSTAGE;
        cp_wait<1>();
        __syncthreads();
        if (kb + 2 < BL_NKB) load_tiles(kb + 2, (kb + 2) % BL_NSTAGE);
        cp_commit();

        const uint32_t sA = sbase + (uint32_t)s * BL_STAGE;
        const uint32_t sB = sA + 16384;

#pragma unroll
        for (int ks = 0; ks < 2; ks++) {
            uint32_t a[4][4], bh[2][4], bl[2][4];
            const int ca = ks * 2 + (lane >> 4);
            const int cb = ks * 2 + ((lane >> 3) & 1);
#pragma unroll
            for (int mi = 0; mi < 4; mi++) {
                int r = wm + mi * 16 + (lane & 7) + ((lane >> 3) & 1) * 8;
                ldmatrix_x4(a[mi], sA + sw128((uint32_t)(r * 128 + ca * 16)));
            }
#pragma unroll
            for (int nj = 0; nj < 2; nj++) {
                int n = wn + nj * 16 + (lane & 7) + (lane >> 4) * 8;
                ldmatrix_x4(bh[nj], sB + sw128((uint32_t)(n * 128 + cb * 16)));
                ldmatrix_x4(bl[nj], sB + sw128((uint32_t)(n * 128 + (cb + 4) * 16)));
            }
#pragma unroll
            for (int nj = 0; nj < 2; nj++)
#pragma unroll
                for (int mi = 0; mi < 4; mi++) {
                    mma16816(acc[mi][nj * 2],     a[mi], bh[nj][0], bh[nj][1]);
                    mma16816(acc[mi][nj * 2 + 1], a[mi], bh[nj][2], bh[nj][3]);
                    mma16816(acc[mi][nj * 2],     a[mi], bl[nj][0], bl[nj][1]);
                    mma16816(acc[mi][nj * 2 + 1], a[mi], bl[nj][2], bl[nj][3]);
                }
#pragma unroll
            for (int mi = 0; mi < 4; mi++) {
                int r = wm + mi * 16 + (lane & 7) + ((lane >> 3) & 1) * 8;
                ldmatrix_x4(a[mi], sA + sw128((uint32_t)(r * 128 + (ca + 4) * 16)));
            }
#pragma unroll
            for (int nj = 0; nj < 2; nj++)
#pragma unroll
                for (int mi = 0; mi < 4; mi++) {
                    mma16816(acc[mi][nj * 2],     a[mi], bh[nj][0], bh[nj][1]);
                    mma16816(acc[mi][nj * 2 + 1], a[mi], bh[nj][2], bh[nj][3]);
                }
        }
    }

    // Epilogue: sigmoid(z) = 0.5*tanh(0.5*(z+bias)) + 0.5  (1 MUFU / element)
    const float hb = 0.5f * bias[0];
    float* obase = out + (size_t)b * L * L;
#pragma unroll
    for (int mi = 0; mi < 4; mi++) {
        int r0 = row0 + wm + mi * 16 + (lane >> 2);
#pragma unroll
        for (int ni = 0; ni < 4; ni++) {
            int col = col0 + wn + ni * 8 + (lane & 3) * 2;
            if (col >= L) continue;
#pragma unroll
            for (int h = 0; h < 2; h++) {
                int row = r0 + h * 8;
                if (row >= L) continue;
                float zh0 = fmaf(acc[mi][ni][h * 2],     0.5f, hb);
                float zh1 = fmaf(acc[mi][ni][h * 2 + 1], 0.5f, hb);
                float2 o;
                o.x = fast_sigmoid_half(zh0);
                o.y = fast_sigmoid_half(zh1);
                *reinterpret_cast<float2*>(&obase[(size_t)row * L + col]) = o;
            }
        }
    }
}

// ---------------------------------------------------------------------------
extern "C" void kernel_launch(void* const* d_in, const int* in_sizes, int n_in,
                              void* d_out, int out_size)
{
    const float* x    = (const float*)d_in[0];   // (8, 2050, 320)
    const float* W    = (const float*)d_in[1];   // (320, 320)
    const float* bias = (const float*)d_in[2];   // (1,)
    float* out = (float*)d_out;                  // (8, 2050, 2050)

    cudaFuncSetAttribute(xw_mma, cudaFuncAttributeMaxDynamicSharedMemorySize, 2 * XW_STAGE);
    cudaFuncSetAttribute(bilinear_mma, cudaFuncAttributeMaxDynamicSharedMemorySize,
                         BL_NSTAGE * BL_STAGE);

    {
        int ntot = NX4 + NW;
        split_pack_kernel<<<(ntot + 255) / 256, 256>>>(x, W);
    }
    {
        dim3 grid(D / 64, (MTOT + 127) / 128);            // (5, 129)
        xw_mma<<<grid, 256, 2 * XW_STAGE>>>();
    }
    {
        dim3 grid((L + 127) / 128, (L + 127) / 128, NB);  // (17,17,8)
        bilinear_mma<<<grid, 256, BL_NSTAGE * BL_STAGE>>>(bias, out);
    }
}